// round 15
// baseline (speedup 1.0000x reference)
#include <cuda_runtime.h>
#include <cuda_fp16.h>
#include <math.h>
#include <stdint.h>

// Problem dims (fixed by the reference)
#define B_ 4
#define S_ 2048
#define E_ 2048
#define H_ 16
#define D_ 128
#define M_ (B_ * S_)        // 8192 tokens
#define NQKV_ (3 * H_ * D_) // 6144
#define HD_ (H_ * D_)       // 2048

// Scratch (allocation-free rule: __device__ globals)
__device__ float g_qkv[(size_t)M_ * NQKV_];      // q,k fp32 (V bypasses)
__device__ __half g_ah[(size_t)M_ * E_];         // GEMM A hi (x / attn out)
__device__ __half g_bh[(size_t)NQKV_ * E_];      // GEMM B^T hi [N,K]
__device__ __half g_qh[(size_t)M_ * HD_];        // q hi (unscaled)
__device__ __half g_kh[(size_t)M_ * HD_];        // k hi
__device__ __half g_vh[(size_t)M_ * HD_];        // v hi
__device__ float g_cos[(size_t)S_ * D_];         // RoPE tables
__device__ float g_sin[(size_t)S_ * D_];

// ---------------------------------------------------------------------------
// Helpers
// ---------------------------------------------------------------------------
__device__ __forceinline__ uint32_t smem_u32(const void* p) {
    uint32_t a;
    asm("{ .reg .u64 t; cvta.to.shared.u64 t, %1; cvt.u32.u64 %0, t; }"
        : "=r"(a) : "l"(p));
    return a;
}
__device__ __forceinline__ void cp16(uint32_t s, const void* g) {
    asm volatile("cp.async.cg.shared.global [%0], [%1], 16;\n" :: "r"(s), "l"(g));
}
__device__ __forceinline__ void cp_commit() {
    asm volatile("cp.async.commit_group;\n" ::: "memory");
}
template <int N>
__device__ __forceinline__ void cp_wait() {
    asm volatile("cp.async.wait_group %0;\n" :: "n"(N) : "memory");
}
__device__ __forceinline__ void ldmx4(uint32_t a, uint32_t& r0, uint32_t& r1,
                                      uint32_t& r2, uint32_t& r3) {
    asm volatile("ldmatrix.sync.aligned.m8n8.x4.shared.b16 {%0,%1,%2,%3}, [%4];"
                 : "=r"(r0), "=r"(r1), "=r"(r2), "=r"(r3) : "r"(a));
}
__device__ __forceinline__ void ldmx4t(uint32_t a, uint32_t& r0, uint32_t& r1,
                                       uint32_t& r2, uint32_t& r3) {
    asm volatile("ldmatrix.sync.aligned.m8n8.x4.trans.shared.b16 {%0,%1,%2,%3}, [%4];"
                 : "=r"(r0), "=r"(r1), "=r"(r2), "=r"(r3) : "r"(a));
}
__device__ __forceinline__ void mma16816(float* c, uint32_t a0, uint32_t a1,
                                         uint32_t a2, uint32_t a3, uint32_t b0,
                                         uint32_t b1) {
    asm volatile(
        "mma.sync.aligned.m16n8k16.row.col.f32.f16.f16.f32 "
        "{%0,%1,%2,%3}, {%4,%5,%6,%7}, {%8,%9}, {%0,%1,%2,%3};"
        : "+f"(c[0]), "+f"(c[1]), "+f"(c[2]), "+f"(c[3])
        : "r"(a0), "r"(a1), "r"(a2), "r"(a3), "r"(b0), "r"(b1));
}

// ---------------------------------------------------------------------------
// Split kernels (fp16, hi only)
// ---------------------------------------------------------------------------
__global__ void __launch_bounds__(256) splitAh(
    const float* __restrict__ X, __half* __restrict__ Yh) {
    int i4 = (blockIdx.x * 256 + threadIdx.x) * 4;
    float4 v = *(const float4*)&X[i4];
    *(__half2*)&Yh[i4] = __floats2half2_rn(v.x, v.y);
    *(__half2*)&Yh[i4 + 2] = __floats2half2_rn(v.z, v.w);
}

// B[K,N] fp32 -> hi [N,K] fp16 (transpose)
__global__ void __launch_bounds__(256) splitTBh(
    const float* __restrict__ B, __half* __restrict__ Yh, int K, int N) {
    __shared__ float t[32][33];
    const int k0 = blockIdx.y * 32, n0 = blockIdx.x * 32;
    const int tx = threadIdx.x, ty = threadIdx.y;
#pragma unroll
    for (int i = 0; i < 32; i += 8)
        t[ty + i][tx] = B[(size_t)(k0 + ty + i) * N + n0 + tx];
    __syncthreads();
#pragma unroll
    for (int i = 0; i < 32; i += 8)
        Yh[(size_t)(n0 + ty + i) * K + k0 + tx] = __float2half(t[tx][ty + i]);
}

__global__ void __launch_bounds__(128) rope_tab() {
    const int s = blockIdx.x;
    const int d = threadIdx.x;
    const int i2 = d & 63;
    float inv = powf(10000.0f, -(float)(2 * i2) * (1.0f / 128.0f));
    float sn, cs;
    sincosf((float)s * inv, &sn, &cs);
    g_cos[(size_t)s * D_ + d] = cs;
    g_sin[(size_t)s * D_ + d] = sn;
}

// ---------------------------------------------------------------------------
// fp16 1-term HMMA GEMM: C = Ah*Bh. CTA tile 128x256, warp tile 64x64
// (8 warps as 2x4), BK=32, 4-stage ring, single sync per chunk.
// MODE 0 (proj): fp32 store (ldC).
// MODE 2 (qkv):  global cols >= 4096 are V -> fp16 hi in-register; else fp32.
// ---------------------------------------------------------------------------
#define BM 128
#define BN 256
#define BK 32
#define TILE_A (BM * 64)               // 8192
#define TILE_BB (BN * 64)              // 16384
#define STAGE_B (TILE_A + TILE_BB)     // 24576
#define GSTAGES 4
#define GEMM_SMEM (GSTAGES * STAGE_B)  // 98304

__device__ __forceinline__ uint32_t swz(int r, int c) {
    return (uint32_t)(r * 64 + ((c ^ ((r >> 1) & 3)) << 4));
}

template <int MODE>
__global__ void __launch_bounds__(256, 1) hgemm_f16(
    const __half* __restrict__ Ah, const __half* __restrict__ Bh,
    float* __restrict__ C, int N, int K, int ldC) {
    extern __shared__ char smem[];
    const uint32_t sb = smem_u32(smem);
    const int tid = threadIdx.x;
    const int wid = tid >> 5;
    const int lane = tid & 31;
    const int wm = wid & 1;    // 2 M groups of 64
    const int wn = wid >> 1;   // 4 N groups of 64
    const int NC = K / BK;

    const int nbx = N / BN;
    const int width = 8 * nbx;
    const int group = blockIdx.x / width;
    const int ig = blockIdx.x % width;
    const int rowBase = (group * 8 + (ig & 7)) * BM;
    const int colBase = (ig >> 3) * BN;

    const int lr = tid >> 2;         // 0..63
    const int lc = tid & 3;
    const int lce = lc * 8;

    auto load_chunk = [&](int ck, int stg) {
        const int k0 = ck * BK;
        const uint32_t st = sb + stg * STAGE_B;
#pragma unroll
        for (int rr = 0; rr < 2; rr++) {
            int r = lr + rr * 64;
            cp16(st + swz(r, lc), Ah + (size_t)(rowBase + r) * K + k0 + lce);
        }
#pragma unroll
        for (int rr = 0; rr < 4; rr++) {
            int r = lr + rr * 64;
            cp16(st + TILE_A + swz(r, lc), Bh + (size_t)(colBase + r) * K + k0 + lce);
        }
        cp_commit();
    };

    load_chunk(0, 0);
    load_chunk(1, 1);
    load_chunk(2, 2);

    float acc[4][8][4];
#pragma unroll
    for (int i = 0; i < 4; i++)
#pragma unroll
        for (int j = 0; j < 8; j++)
#pragma unroll
            for (int q = 0; q < 4; q++) acc[i][j][q] = 0.0f;

    const int aR = wm * 64 + (lane & 15);                        // + mt*16
    const int aC = (lane >> 4);                                  // + ks*2
    const int bR = wn * 64 + (lane & 7) + ((lane >> 4) & 1) * 8; // + ntp*16
    const int bC = ((lane >> 3) & 1);                            // + ks*2

    for (int ck = 0; ck < NC; ck++) {
        if (ck + 3 <= NC) cp_wait<2>();
        else if (ck + 2 <= NC) cp_wait<1>();
        else cp_wait<0>();
        __syncthreads();
        if (ck + 3 < NC) load_chunk(ck + 3, (ck + 3) % GSTAGES);

        const uint32_t st = sb + (ck % GSTAGES) * STAGE_B;
        const uint32_t sAh = st, sBh = st + TILE_A;

#pragma unroll
        for (int ks = 0; ks < 2; ks++) {
            uint32_t a[4][4];
#pragma unroll
            for (int mt = 0; mt < 4; mt++)
                ldmx4(sAh + swz(aR + mt * 16, aC + ks * 2),
                      a[mt][0], a[mt][1], a[mt][2], a[mt][3]);
#pragma unroll
            for (int ntp = 0; ntp < 4; ntp++) {
                uint32_t b0, b1, b2, b3;
                ldmx4(sBh + swz(bR + ntp * 16, bC + ks * 2), b0, b1, b2, b3);
#pragma unroll
                for (int mt = 0; mt < 4; mt++) {
                    mma16816(acc[mt][2 * ntp], a[mt][0], a[mt][1], a[mt][2], a[mt][3], b0, b1);
                    mma16816(acc[mt][2 * ntp + 1], a[mt][0], a[mt][1], a[mt][2], a[mt][3], b2, b3);
                }
            }
        }
    }

    if (MODE == 2 && colBase >= 2 * HD_) {
        // V tiles (global cols 4096..6143): fp16 hi, straight from registers.
#pragma unroll
        for (int mt = 0; mt < 4; mt++) {
            const int row0 = rowBase + wm * 64 + mt * 16 + (lane >> 2);
#pragma unroll
            for (int nt = 0; nt < 8; nt++) {
                const int colg = colBase + wn * 64 + nt * 8 + (lane & 3) * 2;
                const int h = (colg >> 7) & 15;
                const int d = colg & 127;
                const size_t ob0 = (size_t)row0 * HD_ + h * D_ + d;
                *(__half2*)&g_vh[ob0] = __floats2half2_rn(acc[mt][nt][0], acc[mt][nt][1]);
                *(__half2*)&g_vh[ob0 + 8 * HD_] =
                    __floats2half2_rn(acc[mt][nt][2], acc[mt][nt][3]);
            }
        }
    } else {
#pragma unroll
        for (int mt = 0; mt < 4; mt++) {
            const int row0 = rowBase + wm * 64 + mt * 16 + lane / 4;
#pragma unroll
            for (int nt = 0; nt < 8; nt++) {
                const int col = colBase + wn * 64 + nt * 8 + (lane & 3) * 2;
                float2* p0 = (float2*)&C[(size_t)row0 * ldC + col];
                float2* p1 = (float2*)&C[(size_t)(row0 + 8) * ldC + col];
                *p0 = make_float2(acc[mt][nt][0], acc[mt][nt][1]);
                *p1 = make_float2(acc[mt][nt][2], acc[mt][nt][3]);
            }
        }
    }
}

// ---------------------------------------------------------------------------
// Warp-vectorized RMSNorm + RoPE. q -> fp16 hi, k -> fp16 hi.
// ---------------------------------------------------------------------------
__global__ void __launch_bounds__(256) norm_rope2(
    const float* __restrict__ qw, const float* __restrict__ kw) {
    const int idx = blockIdx.x * 8 + (threadIdx.x >> 5);
    const int lane = threadIdx.x & 31;
    const int m = idx >> 5;
    const int rem = idx & 31;
    const int kind = rem >> 4;  // 0=q 1=k
    const int h = rem & 15;
    const int s = m & (S_ - 1);

    const float4 v = *(const float4*)&g_qkv[(size_t)m * NQKV_ +
                                            (size_t)kind * HD_ + h * D_ + lane * 4];
    float ss = v.x * v.x + v.y * v.y + v.z * v.z + v.w * v.w;
#pragma unroll
    for (int off = 16; off > 0; off >>= 1)
        ss += __shfl_xor_sync(0xffffffffu, ss, off);
    const float rn = rsqrtf(ss * (1.0f / 128.0f) + 0.01f);

    const float* w = kind ? kw : qw;
    const float4 w4 = *(const float4*)&w[lane * 4];
    float val[4] = {v.x * rn * w4.x, v.y * rn * w4.y,
                    v.z * rn * w4.z, v.w * rn * w4.w};
    const float sgn = (lane < 16) ? -1.0f : 1.0f;
    float rot[4];
#pragma unroll
    for (int j = 0; j < 4; j++)
        rot[j] = sgn * __shfl_xor_sync(0xffffffffu, val[j], 16);

    const float4 cs4 = *(const float4*)&g_cos[(size_t)s * D_ + lane * 4];
    const float4 sn4 = *(const float4*)&g_sin[(size_t)s * D_ + lane * 4];
    float o[4];
    o[0] = val[0] * cs4.x + rot[0] * sn4.x;
    o[1] = val[1] * cs4.y + rot[1] * sn4.y;
    o[2] = val[2] * cs4.z + rot[2] * sn4.z;
    o[3] = val[3] * cs4.w + rot[3] * sn4.w;

    __half* dst = kind ? g_kh : g_qh;
    const size_t ob = (size_t)m * HD_ + h * D_ + lane * 4;
    *(__half2*)&dst[ob] = __floats2half2_rn(o[0], o[1]);
    *(__half2*)&dst[ob + 2] = __floats2half2_rn(o[2], o[3]);
}

// ---------------------------------------------------------------------------
// fp16 flash attention (round 14 structure, unchanged)
// ---------------------------------------------------------------------------
#define QMAT (128 * 256)
#define FMAT (64 * 256)
#define FSTG (2 * FMAT)
#define FLASH_SMEM (QMAT + 4 * FSTG)

__device__ __forceinline__ uint32_t fswz(int r, int c) {
    return (uint32_t)(r * 256 + ((c ^ (r & 7)) << 4));
}

__global__ void __launch_bounds__(256, 1) flash_mma() {
    extern __shared__ char smc[];
    const uint32_t sb = smem_u32(smc);
    const uint32_t sKV = sb + QMAT;

    const int tid = threadIdx.x;
    const int wid = tid >> 5;
    const int lane = tid & 31;
    const int bh = blockIdx.y;
    const int b = bh >> 4;
    const int h = bh & 15;
    const int iTile = (gridDim.x - 1) - blockIdx.x;
    const int rowBase = iTile * 128;
    const int numIters = 2 * iTile + 2;
    const int g = lane >> 2;
    const int t = lane & 3;
    const float SCALE = 0.08838834764831845f;

    {
#pragma unroll
        for (int it = 0; it < 8; it++) {
            int i = tid + it * 256;
            int r = (i >> 4) & 127;
            int c = i & 15;
            const __half* src = g_qh +
                (size_t)(b * S_ + rowBase + r) * HD_ + h * D_ + c * 8;
            cp16(sb + fswz(r, c), src);
        }
        cp_commit();
    }
    auto load_kv = [&](int jt, int stage) {
        const uint32_t st = sKV + stage * FSTG;
#pragma unroll
        for (int it = 0; it < 8; it++) {
            int i = tid + it * 256;
            int mat = i >> 10;
            int r = (i >> 4) & 63;
            int c = i & 15;
            const __half* src = (mat == 0 ? g_kh : g_vh) +
                (size_t)(b * S_ + jt * 64 + r) * HD_ + h * D_ + c * 8;
            cp16(st + mat * FMAT + fswz(r, c), src);
        }
        cp_commit();
    };
    load_kv(0, 0);
    load_kv(1, 1);
    if (numIters > 2) load_kv(2, 2);

    uint32_t qh[8][4];
    {
        if (numIters > 2) cp_wait<3>(); else cp_wait<2>();
        __syncthreads();
        const int qR = wid * 16 + (lane & 15);
        const int qC = (lane >> 4);
#pragma unroll
        for (int kt = 0; kt < 8; kt++)
            ldmx4(sb + fswz(qR, qC + kt * 2), qh[kt][0], qh[kt][1], qh[kt][2], qh[kt][3]);
    }

    float o[16][4];
#pragma unroll
    for (int nt = 0; nt < 16; nt++)
#pragma unroll
        for (int q = 0; q < 4; q++) o[nt][q] = 0.0f;
    float m_i[2] = {-1e30f, -1e30f};
    float l_i[2] = {0.0f, 0.0f};

    const int warpRow0 = rowBase + wid * 16;
    const int kRow = (lane & 7) + ((lane >> 4) & 1) * 8;
    const int kC = (lane >> 3) & 1;
    const int vRow = (lane & 7) + ((lane >> 3) & 1) * 8;
    const int vC = (lane >> 4) & 1;

    for (int jt = 0; jt < numIters; jt++) {
        if (jt + 3 <= numIters) cp_wait<2>();
        else if (jt + 2 <= numIters) cp_wait<1>();
        else cp_wait<0>();
        __syncthreads();
        if (jt + 3 < numIters) load_kv(jt + 3, (jt + 3) & 3);

        const int jBase = jt * 64;
        const bool active = (jBase <= warpRow0 + 15);
        if (active) {
            const uint32_t st = sKV + (jt & 3) * FSTG;
            const uint32_t Kh = st, Vh = st + FMAT;

            float s[8][4];
#pragma unroll
            for (int nt = 0; nt < 8; nt++)
#pragma unroll
                for (int q = 0; q < 4; q++) s[nt][q] = 0.0f;

#pragma unroll
            for (int kt = 0; kt < 8; kt++) {
#pragma unroll
                for (int ntp = 0; ntp < 4; ntp++) {
                    uint32_t b0, b1, b2, b3;
                    ldmx4(Kh + fswz(ntp * 16 + kRow, kC + kt * 2), b0, b1, b2, b3);
                    mma16816(s[2 * ntp], qh[kt][0], qh[kt][1], qh[kt][2], qh[kt][3], b0, b1);
                    mma16816(s[2 * ntp + 1], qh[kt][0], qh[kt][1], qh[kt][2], qh[kt][3], b2, b3);
                }
            }

#pragma unroll
            for (int nt = 0; nt < 8; nt++)
#pragma unroll
                for (int q = 0; q < 4; q++) s[nt][q] *= SCALE;

            if (jBase + 63 > warpRow0) {
#pragma unroll
                for (int nt = 0; nt < 8; nt++) {
                    int col = jBase + nt * 8 + 2 * t;
                    int r0 = warpRow0 + g, r1 = warpRow0 + g + 8;
                    if (col > r0) s[nt][0] = -1e30f;
                    if (col + 1 > r0) s[nt][1] = -1e30f;
                    if (col > r1) s[nt][2] = -1e30f;
                    if (col + 1 > r1) s[nt][3] = -1e30f;
                }
            }

#pragma unroll
            for (int h2 = 0; h2 < 2; h2++) {
                float tm = -1e30f;
#pragma unroll
                for (int nt = 0; nt < 8; nt++)
                    tm = fmaxf(tm, fmaxf(s[nt][2 * h2], s[nt][2 * h2 + 1]));
                tm = fmaxf(tm, __shfl_xor_sync(0xffffffffu, tm, 1));
                tm = fmaxf(tm, __shfl_xor_sync(0xffffffffu, tm, 2));
                float mnew = fmaxf(m_i[h2], tm);
                float rs = 0.0f;
#pragma unroll
                for (int nt = 0; nt < 8; nt++) {
                    float p0 = __expf(s[nt][2 * h2] - mnew);
                    float p1 = __expf(s[nt][2 * h2 + 1] - mnew);
                    s[nt][2 * h2] = p0;
                    s[nt][2 * h2 + 1] = p1;
                    rs += p0 + p1;
                }
                rs += __shfl_xor_sync(0xffffffffu, rs, 1);
                rs += __shfl_xor_sync(0xffffffffu, rs, 2);
                float alpha = __expf(m_i[h2] - mnew);
                m_i[h2] = mnew;
                l_i[h2] = l_i[h2] * alpha + rs;
#pragma unroll
                for (int nt = 0; nt < 16; nt++) {
                    o[nt][2 * h2] *= alpha;
                    o[nt][2 * h2 + 1] *= alpha;
                }
            }

#pragma unroll
            for (int kk = 0; kk < 4; kk++) {
                uint32_t ph0, ph1, ph2, ph3;
                {
                    __half2 x;
                    x = __floats2half2_rn(s[2 * kk][0], s[2 * kk][1]);
                    ph0 = *(uint32_t*)&x;
                    x = __floats2half2_rn(s[2 * kk][2], s[2 * kk][3]);
                    ph1 = *(uint32_t*)&x;
                    x = __floats2half2_rn(s[2 * kk + 1][0], s[2 * kk + 1][1]);
                    ph2 = *(uint32_t*)&x;
                    x = __floats2half2_rn(s[2 * kk + 1][2], s[2 * kk + 1][3]);
                    ph3 = *(uint32_t*)&x;
                }
#pragma unroll
                for (int np = 0; np < 8; np++) {
                    uint32_t v0, v1, v2, v3;
                    ldmx4t(Vh + fswz(kk * 16 + vRow, vC + np * 2), v0, v1, v2, v3);
                    mma16816(o[2 * np], ph0, ph1, ph2, ph3, v0, v1);
                    mma16816(o[2 * np + 1], ph0, ph1, ph2, ph3, v2, v3);
                }
            }
        }
    }

#pragma unroll
    for (int h2 = 0; h2 < 2; h2++) {
        float linv = 1.0f / l_i[h2];
        size_t mrow = (size_t)(b * S_ + warpRow0 + g + 8 * h2);
#pragma unroll
        for (int nt = 0; nt < 16; nt++) {
            float v0 = o[nt][2 * h2] * linv;
            float v1 = o[nt][2 * h2 + 1] * linv;
            size_t base = mrow * HD_ + h * D_ + nt * 8 + 2 * t;
            *(__half2*)&g_ah[base] = __floats2half2_rn(v0, v1);
        }
    }
}

// ---------------------------------------------------------------------------
// Launcher (stream-forked graph; single homogeneous QKV GEMM)
// ---------------------------------------------------------------------------
extern "C" void kernel_launch(void* const* d_in, const int* in_sizes, int n_in,
                              void* d_out, int out_size) {
    const float* x = (const float*)d_in[0];
    const float* wqkv = (const float*)d_in[1];
    const float* wproj = (const float*)d_in[2];
    const float* qw = (const float*)d_in[3];
    const float* kw = (const float*)d_in[4];
    float* out = (float*)d_out;

    void *p_qkv, *p_ah, *p_bh;
    cudaGetSymbolAddress(&p_qkv, g_qkv);
    cudaGetSymbolAddress(&p_ah, g_ah);
    cudaGetSymbolAddress(&p_bh, g_bh);

    cudaFuncSetAttribute(hgemm_f16<0>, cudaFuncAttributeMaxDynamicSharedMemorySize,
                         GEMM_SMEM);
    cudaFuncSetAttribute(hgemm_f16<2>, cudaFuncAttributeMaxDynamicSharedMemorySize,
                         GEMM_SMEM);
    cudaFuncSetAttribute(flash_mma, cudaFuncAttributeMaxDynamicSharedMemorySize,
                         FLASH_SMEM);

    cudaStream_t s1;
    cudaStreamCreate(&s1);
    cudaEvent_t eFork, eW1, eW2;
    cudaEventCreateWithFlags(&eFork, cudaEventDisableTiming);
    cudaEventCreateWithFlags(&eW1, cudaEventDisableTiming);
    cudaEventCreateWithFlags(&eW2, cudaEventDisableTiming);

    cudaEventRecord(eFork, 0);
    cudaStreamWaitEvent(s1, eFork, 0);

    // Side stream: RoPE tables + wqkv split.
    rope_tab<<<S_, 128, 0, s1>>>();
    splitTBh<<<dim3(NQKV_ / 32, E_ / 32), dim3(32, 8), 0, s1>>>(
        wqkv, (__half*)p_bh, E_, NQKV_);
    cudaEventRecord(eW1, s1);

    // Main stream: activation split (hi only).
    splitAh<<<(M_ * E_) / 1024, 256>>>(x, (__half*)p_ah);

    // Join, then the single homogeneous QKV GEMM (1-term, N=6144).
    cudaStreamWaitEvent(0, eW1, 0);
    hgemm_f16<2><<<(NQKV_ / BN) * (M_ / BM), 256, GEMM_SMEM>>>(
        (const __half*)p_ah, (const __half*)p_bh,
        (float*)p_qkv, NQKV_, E_, NQKV_);

    // Side stream: wproj split overlaps norm/flash (ordered after QKV GEMM).
    cudaEventRecord(eFork, 0);
    cudaStreamWaitEvent(s1, eFork, 0);
    splitTBh<<<dim3(E_ / 32, HD_ / 32), dim3(32, 8), 0, s1>>>(
        wproj, (__half*)p_bh, HD_, E_);
    cudaEventRecord(eW2, s1);

    // Main stream: norm + flash.
    norm_rope2<<<(M_ * H_ * 2) / 8, 256>>>(qw, kw);
    flash_mma<<<dim3(S_ / 128, B_ * H_), 256, FLASH_SMEM>>>();

    // Join and run output projection (1-term).
    cudaStreamWaitEvent(0, eW2, 0);
    hgemm_f16<0><<<(E_ / BN) * (M_ / BM), 256, GEMM_SMEM>>>(
        (const __half*)p_ah, (const __half*)p_bh,
        out, E_, HD_, E_);
    // Streams/events intentionally not destroyed (graph-capture safety).
}

// round 16
// speedup vs baseline: 1.2718x; 1.2718x over previous
#include <cuda_runtime.h>
#include <cuda_fp16.h>
#include <math.h>
#include <stdint.h>

// Problem dims (fixed by the reference)
#define B_ 4
#define S_ 2048
#define E_ 2048
#define H_ 16
#define D_ 128
#define M_ (B_ * S_)        // 8192 tokens
#define NQKV_ (3 * H_ * D_) // 6144
#define HD_ (H_ * D_)       // 2048

// Scratch (allocation-free rule: __device__ globals)
__device__ float g_qkv[(size_t)M_ * NQKV_];      // q,k fp32 (V bypasses)
__device__ __half g_ah[(size_t)M_ * E_];         // GEMM A hi (x / attn out)
__device__ __half g_bh[(size_t)NQKV_ * E_];      // GEMM B^T hi [N,K]
__device__ __half g_qh[(size_t)M_ * HD_];        // q hi (unscaled)
__device__ __half g_kh[(size_t)M_ * HD_];        // k hi
__device__ __half g_vh[(size_t)M_ * HD_];        // v hi
__device__ float g_cos[(size_t)S_ * D_];         // RoPE tables
__device__ float g_sin[(size_t)S_ * D_];

// ---------------------------------------------------------------------------
// Helpers
// ---------------------------------------------------------------------------
__device__ __forceinline__ uint32_t smem_u32(const void* p) {
    uint32_t a;
    asm("{ .reg .u64 t; cvta.to.shared.u64 t, %1; cvt.u32.u64 %0, t; }"
        : "=r"(a) : "l"(p));
    return a;
}
__device__ __forceinline__ void cp16(uint32_t s, const void* g) {
    asm volatile("cp.async.cg.shared.global [%0], [%1], 16;\n" :: "r"(s), "l"(g));
}
__device__ __forceinline__ void cp_commit() {
    asm volatile("cp.async.commit_group;\n" ::: "memory");
}
template <int N>
__device__ __forceinline__ void cp_wait() {
    asm volatile("cp.async.wait_group %0;\n" :: "n"(N) : "memory");
}
__device__ __forceinline__ void ldmx4(uint32_t a, uint32_t& r0, uint32_t& r1,
                                      uint32_t& r2, uint32_t& r3) {
    asm volatile("ldmatrix.sync.aligned.m8n8.x4.shared.b16 {%0,%1,%2,%3}, [%4];"
                 : "=r"(r0), "=r"(r1), "=r"(r2), "=r"(r3) : "r"(a));
}
__device__ __forceinline__ void ldmx4t(uint32_t a, uint32_t& r0, uint32_t& r1,
                                       uint32_t& r2, uint32_t& r3) {
    asm volatile("ldmatrix.sync.aligned.m8n8.x4.trans.shared.b16 {%0,%1,%2,%3}, [%4];"
                 : "=r"(r0), "=r"(r1), "=r"(r2), "=r"(r3) : "r"(a));
}
__device__ __forceinline__ void mma16816(float* c, uint32_t a0, uint32_t a1,
                                         uint32_t a2, uint32_t a3, uint32_t b0,
                                         uint32_t b1) {
    asm volatile(
        "mma.sync.aligned.m16n8k16.row.col.f32.f16.f16.f32 "
        "{%0,%1,%2,%3}, {%4,%5,%6,%7}, {%8,%9}, {%0,%1,%2,%3};"
        : "+f"(c[0]), "+f"(c[1]), "+f"(c[2]), "+f"(c[3])
        : "r"(a0), "r"(a1), "r"(a2), "r"(a3), "r"(b0), "r"(b1));
}

// ---------------------------------------------------------------------------
// Split kernels (fp16, hi only)
// ---------------------------------------------------------------------------
__global__ void __launch_bounds__(256) splitAh(
    const float* __restrict__ X, __half* __restrict__ Yh) {
    int i4 = (blockIdx.x * 256 + threadIdx.x) * 4;
    float4 v = *(const float4*)&X[i4];
    *(__half2*)&Yh[i4] = __floats2half2_rn(v.x, v.y);
    *(__half2*)&Yh[i4 + 2] = __floats2half2_rn(v.z, v.w);
}

// B[K,N] fp32 -> hi [N,K] fp16 (transpose)
__global__ void __launch_bounds__(256) splitTBh(
    const float* __restrict__ B, __half* __restrict__ Yh, int K, int N) {
    __shared__ float t[32][33];
    const int k0 = blockIdx.y * 32, n0 = blockIdx.x * 32;
    const int tx = threadIdx.x, ty = threadIdx.y;
#pragma unroll
    for (int i = 0; i < 32; i += 8)
        t[ty + i][tx] = B[(size_t)(k0 + ty + i) * N + n0 + tx];
    __syncthreads();
#pragma unroll
    for (int i = 0; i < 32; i += 8)
        Yh[(size_t)(n0 + ty + i) * K + k0 + tx] = __float2half(t[tx][ty + i]);
}

__global__ void __launch_bounds__(128) rope_tab() {
    const int s = blockIdx.x;
    const int d = threadIdx.x;
    const int i2 = d & 63;
    float inv = powf(10000.0f, -(float)(2 * i2) * (1.0f / 128.0f));
    float sn, cs;
    sincosf((float)s * inv, &sn, &cs);
    g_cos[(size_t)s * D_ + d] = cs;
    g_sin[(size_t)s * D_ + d] = sn;
}

// ---------------------------------------------------------------------------
// fp16 1-term HMMA GEMM: C = Ah*Bh. CTA tile 128x128, 128 threads / 4 warps
// (2x2 of 64x64 warp tiles), BK=32, 4-stage ring, 2 CTA/SM, single sync.
// MODE 0 (proj): fp32 store (ldC).
// MODE 2 (qkv):  slices >=32 are V -> fp16 hi in-register; else fp32 (ldC).
// ---------------------------------------------------------------------------
#define BM 128
#define BN 128
#define BK 32
#define TILE_B (BM * 64)               // 8192
#define GSTAGES 4
#define STAGE_B (2 * TILE_B)           // Ah,Bh = 16384
#define GEMM_SMEM (GSTAGES * STAGE_B)  // 65536

__device__ __forceinline__ uint32_t swz(int r, int c) {
    return (uint32_t)(r * 64 + ((c ^ ((r >> 1) & 3)) << 4));
}

template <int MODE>
__global__ void __launch_bounds__(128, 2) hgemm_f16(
    const __half* __restrict__ Ah, const __half* __restrict__ Bh,
    float* __restrict__ C, int N, int K, int ldC) {
    extern __shared__ char smem[];
    const uint32_t sb = smem_u32(smem);
    const int tid = threadIdx.x;
    const int wid = tid >> 5;
    const int lane = tid & 31;
    const int wm = wid & 1;    // 2 M groups of 64
    const int wn = wid >> 1;   // 2 N groups of 64
    const int NC = K / BK;

    const int nbx = N / BN;
    const int width = 8 * nbx;
    const int group = blockIdx.x / width;
    const int ig = blockIdx.x % width;
    const int rowBase = (group * 8 + (ig & 7)) * BM;
    const int colBase = (ig >> 3) * BN;

    const int lr = tid >> 2;         // 0..31
    const int lc = tid & 3;
    const int lce = lc * 8;

    auto load_chunk = [&](int ck, int stg) {
        const int k0 = ck * BK;
        const uint32_t st = sb + stg * STAGE_B;
#pragma unroll
        for (int rr = 0; rr < 4; rr++) {
            int r = lr + rr * 32;
            cp16(st + swz(r, lc), Ah + (size_t)(rowBase + r) * K + k0 + lce);
            cp16(st + TILE_B + swz(r, lc), Bh + (size_t)(colBase + r) * K + k0 + lce);
        }
        cp_commit();
    };

    load_chunk(0, 0);
    load_chunk(1, 1);
    load_chunk(2, 2);

    float acc[4][8][4];
#pragma unroll
    for (int i = 0; i < 4; i++)
#pragma unroll
        for (int j = 0; j < 8; j++)
#pragma unroll
            for (int q = 0; q < 4; q++) acc[i][j][q] = 0.0f;

    const int aR = wm * 64 + (lane & 15);                        // + mt*16
    const int aC = (lane >> 4);                                  // + ks*2
    const int bR = wn * 64 + (lane & 7) + ((lane >> 4) & 1) * 8; // + ntp*16
    const int bC = ((lane >> 3) & 1);                            // + ks*2

    for (int ck = 0; ck < NC; ck++) {
        if (ck + 3 <= NC) cp_wait<2>();
        else if (ck + 2 <= NC) cp_wait<1>();
        else cp_wait<0>();
        __syncthreads();
        if (ck + 3 < NC) load_chunk(ck + 3, (ck + 3) % GSTAGES);

        const uint32_t st = sb + (ck % GSTAGES) * STAGE_B;
        const uint32_t sAh = st, sBh = st + TILE_B;

#pragma unroll
        for (int ks = 0; ks < 2; ks++) {
            uint32_t a[4][4];
#pragma unroll
            for (int mt = 0; mt < 4; mt++)
                ldmx4(sAh + swz(aR + mt * 16, aC + ks * 2),
                      a[mt][0], a[mt][1], a[mt][2], a[mt][3]);
#pragma unroll
            for (int ntp = 0; ntp < 4; ntp++) {
                uint32_t b0, b1, b2, b3;
                ldmx4(sBh + swz(bR + ntp * 16, bC + ks * 2), b0, b1, b2, b3);
#pragma unroll
                for (int mt = 0; mt < 4; mt++) {
                    mma16816(acc[mt][2 * ntp], a[mt][0], a[mt][1], a[mt][2], a[mt][3], b0, b1);
                    mma16816(acc[mt][2 * ntp + 1], a[mt][0], a[mt][1], a[mt][2], a[mt][3], b2, b3);
                }
            }
        }
    }

    if (MODE == 2 && (colBase >> 7) >= 32) {
        // V tile (slices 32..47): fp16 hi only, straight from registers.
        const int h = (colBase >> 7) & 15;
#pragma unroll
        for (int mt = 0; mt < 4; mt++) {
            const int row0 = rowBase + wm * 64 + mt * 16 + (lane >> 2);
#pragma unroll
            for (int nt = 0; nt < 8; nt++) {
                const int d = wn * 64 + nt * 8 + (lane & 3) * 2;
                const size_t ob0 = (size_t)row0 * HD_ + h * D_ + d;
                *(__half2*)&g_vh[ob0] = __floats2half2_rn(acc[mt][nt][0], acc[mt][nt][1]);
                *(__half2*)&g_vh[ob0 + 8 * HD_] =
                    __floats2half2_rn(acc[mt][nt][2], acc[mt][nt][3]);
            }
        }
    } else {
#pragma unroll
        for (int mt = 0; mt < 4; mt++) {
            const int row0 = rowBase + wm * 64 + mt * 16 + lane / 4;
#pragma unroll
            for (int nt = 0; nt < 8; nt++) {
                const int col = colBase + wn * 64 + nt * 8 + (lane & 3) * 2;
                float2* p0 = (float2*)&C[(size_t)row0 * ldC + col];
                float2* p1 = (float2*)&C[(size_t)(row0 + 8) * ldC + col];
                *p0 = make_float2(acc[mt][nt][0], acc[mt][nt][1]);
                *p1 = make_float2(acc[mt][nt][2], acc[mt][nt][3]);
            }
        }
    }
}

// ---------------------------------------------------------------------------
// Warp-vectorized RMSNorm + RoPE. q -> fp16 hi, k -> fp16 hi.
// ---------------------------------------------------------------------------
__global__ void __launch_bounds__(256) norm_rope2(
    const float* __restrict__ qw, const float* __restrict__ kw) {
    const int idx = blockIdx.x * 8 + (threadIdx.x >> 5);
    const int lane = threadIdx.x & 31;
    const int m = idx >> 5;
    const int rem = idx & 31;
    const int kind = rem >> 4;  // 0=q 1=k
    const int h = rem & 15;
    const int s = m & (S_ - 1);

    const float4 v = *(const float4*)&g_qkv[(size_t)m * NQKV_ +
                                            (size_t)kind * HD_ + h * D_ + lane * 4];
    float ss = v.x * v.x + v.y * v.y + v.z * v.z + v.w * v.w;
#pragma unroll
    for (int off = 16; off > 0; off >>= 1)
        ss += __shfl_xor_sync(0xffffffffu, ss, off);
    const float rn = rsqrtf(ss * (1.0f / 128.0f) + 0.01f);

    const float* w = kind ? kw : qw;
    const float4 w4 = *(const float4*)&w[lane * 4];
    float val[4] = {v.x * rn * w4.x, v.y * rn * w4.y,
                    v.z * rn * w4.z, v.w * rn * w4.w};
    const float sgn = (lane < 16) ? -1.0f : 1.0f;
    float rot[4];
#pragma unroll
    for (int j = 0; j < 4; j++)
        rot[j] = sgn * __shfl_xor_sync(0xffffffffu, val[j], 16);

    const float4 cs4 = *(const float4*)&g_cos[(size_t)s * D_ + lane * 4];
    const float4 sn4 = *(const float4*)&g_sin[(size_t)s * D_ + lane * 4];
    float o[4];
    o[0] = val[0] * cs4.x + rot[0] * sn4.x;
    o[1] = val[1] * cs4.y + rot[1] * sn4.y;
    o[2] = val[2] * cs4.z + rot[2] * sn4.z;
    o[3] = val[3] * cs4.w + rot[3] * sn4.w;

    __half* dst = kind ? g_kh : g_qh;
    const size_t ob = (size_t)m * HD_ + h * D_ + lane * 4;
    *(__half2*)&dst[ob] = __floats2half2_rn(o[0], o[1]);
    *(__half2*)&dst[ob + 2] = __floats2half2_rn(o[2], o[3]);
}

// ---------------------------------------------------------------------------
// fp16 flash attention (round 14 structure, unchanged)
// ---------------------------------------------------------------------------
#define QMAT (128 * 256)
#define FMAT (64 * 256)
#define FSTG (2 * FMAT)
#define FLASH_SMEM (QMAT + 4 * FSTG)

__device__ __forceinline__ uint32_t fswz(int r, int c) {
    return (uint32_t)(r * 256 + ((c ^ (r & 7)) << 4));
}

__global__ void __launch_bounds__(256, 1) flash_mma() {
    extern __shared__ char smc[];
    const uint32_t sb = smem_u32(smc);
    const uint32_t sKV = sb + QMAT;

    const int tid = threadIdx.x;
    const int wid = tid >> 5;
    const int lane = tid & 31;
    const int bh = blockIdx.y;
    const int b = bh >> 4;
    const int h = bh & 15;
    const int iTile = (gridDim.x - 1) - blockIdx.x;
    const int rowBase = iTile * 128;
    const int numIters = 2 * iTile + 2;
    const int g = lane >> 2;
    const int t = lane & 3;
    const float SCALE = 0.08838834764831845f;

    {
#pragma unroll
        for (int it = 0; it < 8; it++) {
            int i = tid + it * 256;
            int r = (i >> 4) & 127;
            int c = i & 15;
            const __half* src = g_qh +
                (size_t)(b * S_ + rowBase + r) * HD_ + h * D_ + c * 8;
            cp16(sb + fswz(r, c), src);
        }
        cp_commit();
    }
    auto load_kv = [&](int jt, int stage) {
        const uint32_t st = sKV + stage * FSTG;
#pragma unroll
        for (int it = 0; it < 8; it++) {
            int i = tid + it * 256;
            int mat = i >> 10;
            int r = (i >> 4) & 63;
            int c = i & 15;
            const __half* src = (mat == 0 ? g_kh : g_vh) +
                (size_t)(b * S_ + jt * 64 + r) * HD_ + h * D_ + c * 8;
            cp16(st + mat * FMAT + fswz(r, c), src);
        }
        cp_commit();
    };
    load_kv(0, 0);
    load_kv(1, 1);
    if (numIters > 2) load_kv(2, 2);

    uint32_t qh[8][4];
    {
        if (numIters > 2) cp_wait<3>(); else cp_wait<2>();
        __syncthreads();
        const int qR = wid * 16 + (lane & 15);
        const int qC = (lane >> 4);
#pragma unroll
        for (int kt = 0; kt < 8; kt++)
            ldmx4(sb + fswz(qR, qC + kt * 2), qh[kt][0], qh[kt][1], qh[kt][2], qh[kt][3]);
    }

    float o[16][4];
#pragma unroll
    for (int nt = 0; nt < 16; nt++)
#pragma unroll
        for (int q = 0; q < 4; q++) o[nt][q] = 0.0f;
    float m_i[2] = {-1e30f, -1e30f};
    float l_i[2] = {0.0f, 0.0f};

    const int warpRow0 = rowBase + wid * 16;
    const int kRow = (lane & 7) + ((lane >> 4) & 1) * 8;
    const int kC = (lane >> 3) & 1;
    const int vRow = (lane & 7) + ((lane >> 3) & 1) * 8;
    const int vC = (lane >> 4) & 1;

    for (int jt = 0; jt < numIters; jt++) {
        if (jt + 3 <= numIters) cp_wait<2>();
        else if (jt + 2 <= numIters) cp_wait<1>();
        else cp_wait<0>();
        __syncthreads();
        if (jt + 3 < numIters) load_kv(jt + 3, (jt + 3) & 3);

        const int jBase = jt * 64;
        const bool active = (jBase <= warpRow0 + 15);
        if (active) {
            const uint32_t st = sKV + (jt & 3) * FSTG;
            const uint32_t Kh = st, Vh = st + FMAT;

            float s[8][4];
#pragma unroll
            for (int nt = 0; nt < 8; nt++)
#pragma unroll
                for (int q = 0; q < 4; q++) s[nt][q] = 0.0f;

#pragma unroll
            for (int kt = 0; kt < 8; kt++) {
#pragma unroll
                for (int ntp = 0; ntp < 4; ntp++) {
                    uint32_t b0, b1, b2, b3;
                    ldmx4(Kh + fswz(ntp * 16 + kRow, kC + kt * 2), b0, b1, b2, b3);
                    mma16816(s[2 * ntp], qh[kt][0], qh[kt][1], qh[kt][2], qh[kt][3], b0, b1);
                    mma16816(s[2 * ntp + 1], qh[kt][0], qh[kt][1], qh[kt][2], qh[kt][3], b2, b3);
                }
            }

#pragma unroll
            for (int nt = 0; nt < 8; nt++)
#pragma unroll
                for (int q = 0; q < 4; q++) s[nt][q] *= SCALE;

            if (jBase + 63 > warpRow0) {
#pragma unroll
                for (int nt = 0; nt < 8; nt++) {
                    int col = jBase + nt * 8 + 2 * t;
                    int r0 = warpRow0 + g, r1 = warpRow0 + g + 8;
                    if (col > r0) s[nt][0] = -1e30f;
                    if (col + 1 > r0) s[nt][1] = -1e30f;
                    if (col > r1) s[nt][2] = -1e30f;
                    if (col + 1 > r1) s[nt][3] = -1e30f;
                }
            }

#pragma unroll
            for (int h2 = 0; h2 < 2; h2++) {
                float tm = -1e30f;
#pragma unroll
                for (int nt = 0; nt < 8; nt++)
                    tm = fmaxf(tm, fmaxf(s[nt][2 * h2], s[nt][2 * h2 + 1]));
                tm = fmaxf(tm, __shfl_xor_sync(0xffffffffu, tm, 1));
                tm = fmaxf(tm, __shfl_xor_sync(0xffffffffu, tm, 2));
                float mnew = fmaxf(m_i[h2], tm);
                float rs = 0.0f;
#pragma unroll
                for (int nt = 0; nt < 8; nt++) {
                    float p0 = __expf(s[nt][2 * h2] - mnew);
                    float p1 = __expf(s[nt][2 * h2 + 1] - mnew);
                    s[nt][2 * h2] = p0;
                    s[nt][2 * h2 + 1] = p1;
                    rs += p0 + p1;
                }
                rs += __shfl_xor_sync(0xffffffffu, rs, 1);
                rs += __shfl_xor_sync(0xffffffffu, rs, 2);
                float alpha = __expf(m_i[h2] - mnew);
                m_i[h2] = mnew;
                l_i[h2] = l_i[h2] * alpha + rs;
#pragma unroll
                for (int nt = 0; nt < 16; nt++) {
                    o[nt][2 * h2] *= alpha;
                    o[nt][2 * h2 + 1] *= alpha;
                }
            }

#pragma unroll
            for (int kk = 0; kk < 4; kk++) {
                uint32_t ph0, ph1, ph2, ph3;
                {
                    __half2 x;
                    x = __floats2half2_rn(s[2 * kk][0], s[2 * kk][1]);
                    ph0 = *(uint32_t*)&x;
                    x = __floats2half2_rn(s[2 * kk][2], s[2 * kk][3]);
                    ph1 = *(uint32_t*)&x;
                    x = __floats2half2_rn(s[2 * kk + 1][0], s[2 * kk + 1][1]);
                    ph2 = *(uint32_t*)&x;
                    x = __floats2half2_rn(s[2 * kk + 1][2], s[2 * kk + 1][3]);
                    ph3 = *(uint32_t*)&x;
                }
#pragma unroll
                for (int np = 0; np < 8; np++) {
                    uint32_t v0, v1, v2, v3;
                    ldmx4t(Vh + fswz(kk * 16 + vRow, vC + np * 2), v0, v1, v2, v3);
                    mma16816(o[2 * np], ph0, ph1, ph2, ph3, v0, v1);
                    mma16816(o[2 * np + 1], ph0, ph1, ph2, ph3, v2, v3);
                }
            }
        }
    }

#pragma unroll
    for (int h2 = 0; h2 < 2; h2++) {
        float linv = 1.0f / l_i[h2];
        size_t mrow = (size_t)(b * S_ + warpRow0 + g + 8 * h2);
#pragma unroll
        for (int nt = 0; nt < 16; nt++) {
            float v0 = o[nt][2 * h2] * linv;
            float v1 = o[nt][2 * h2 + 1] * linv;
            size_t base = mrow * HD_ + h * D_ + nt * 8 + 2 * t;
            *(__half2*)&g_ah[base] = __floats2half2_rn(v0, v1);
        }
    }
}

// ---------------------------------------------------------------------------
// Launcher (stream-forked graph; single homogeneous QKV GEMM)
// ---------------------------------------------------------------------------
extern "C" void kernel_launch(void* const* d_in, const int* in_sizes, int n_in,
                              void* d_out, int out_size) {
    const float* x = (const float*)d_in[0];
    const float* wqkv = (const float*)d_in[1];
    const float* wproj = (const float*)d_in[2];
    const float* qw = (const float*)d_in[3];
    const float* kw = (const float*)d_in[4];
    float* out = (float*)d_out;

    void *p_qkv, *p_ah, *p_bh;
    cudaGetSymbolAddress(&p_qkv, g_qkv);
    cudaGetSymbolAddress(&p_ah, g_ah);
    cudaGetSymbolAddress(&p_bh, g_bh);

    cudaFuncSetAttribute(hgemm_f16<0>, cudaFuncAttributeMaxDynamicSharedMemorySize,
                         GEMM_SMEM);
    cudaFuncSetAttribute(hgemm_f16<2>, cudaFuncAttributeMaxDynamicSharedMemorySize,
                         GEMM_SMEM);
    cudaFuncSetAttribute(flash_mma, cudaFuncAttributeMaxDynamicSharedMemorySize,
                         FLASH_SMEM);

    cudaStream_t s1;
    cudaStreamCreate(&s1);
    cudaEvent_t eFork, eW1, eW2;
    cudaEventCreateWithFlags(&eFork, cudaEventDisableTiming);
    cudaEventCreateWithFlags(&eW1, cudaEventDisableTiming);
    cudaEventCreateWithFlags(&eW2, cudaEventDisableTiming);

    cudaEventRecord(eFork, 0);
    cudaStreamWaitEvent(s1, eFork, 0);

    // Side stream: RoPE tables + wqkv split.
    rope_tab<<<S_, 128, 0, s1>>>();
    splitTBh<<<dim3(NQKV_ / 32, E_ / 32), dim3(32, 8), 0, s1>>>(
        wqkv, (__half*)p_bh, E_, NQKV_);
    cudaEventRecord(eW1, s1);

    // Main stream: activation split (hi only).
    splitAh<<<(M_ * E_) / 1024, 256>>>(x, (__half*)p_ah);

    // Join, then the single homogeneous QKV GEMM (1-term, N=6144).
    cudaStreamWaitEvent(0, eW1, 0);
    hgemm_f16<2><<<(NQKV_ / BN) * (M_ / BM), 128, GEMM_SMEM>>>(
        (const __half*)p_ah, (const __half*)p_bh,
        (float*)p_qkv, NQKV_, E_, NQKV_);

    // Side stream: wproj split overlaps norm/flash (ordered after QKV GEMM).
    cudaEventRecord(eFork, 0);
    cudaStreamWaitEvent(s1, eFork, 0);
    splitTBh<<<dim3(E_ / 32, HD_ / 32), dim3(32, 8), 0, s1>>>(
        wproj, (__half*)p_bh, HD_, E_);
    cudaEventRecord(eW2, s1);

    // Main stream: norm + flash.
    norm_rope2<<<(M_ * H_ * 2) / 8, 256>>>(qw, kw);
    flash_mma<<<dim3(S_ / 128, B_ * H_), 256, FLASH_SMEM>>>();

    // Join and run output projection (1-term).
    cudaStreamWaitEvent(0, eW2, 0);
    hgemm_f16<0><<<(E_ / BN) * (M_ / BM), 128, GEMM_SMEM>>>(
        (const __half*)p_ah, (const __half*)p_bh,
        out, E_, HD_, E_);
    // Streams/events intentionally not destroyed (graph-capture safety).
}